// round 10
// baseline (speedup 1.0000x reference)
#include <cuda_runtime.h>
#include <cuda_fp16.h>

#define NN 50000
#define NE 600000
#define HID 128

#define SCAN_BS 256
#define SCAN_VT 2
#define SCAN_ELEMS (SCAN_BS * SCAN_VT)              // 512
#define SCAN_NBLK ((2 * NN + SCAN_ELEMS - 1) / SCAN_ELEMS)  // 196

#define ASTRIDE 136

typedef unsigned long long u64;
typedef unsigned int u32;
typedef unsigned short u16;

// ---- scratch ----
__device__ int    g_cnt[2 * NN];
__device__ int    g_offs[2 * NN + 1];
__device__ int    g_bsum[256];
__device__ u16    g_csr16[2 * NE];
__device__ float  g_dinv[NN];
__device__ float  g_binv[NN];
__device__ __half g_xh[NN * HID];
__device__ __half g_w1h[HID * HID];
__device__ __half g_w2h[HID * HID];
__device__ __half g_xw[NN * HID];
__device__ __half g_m[NN * HID];
__device__ __half g_h[NN * HID];
__device__ int    g_is_i32;

// ---- streams + events ----
struct SideStream {
    cudaStream_t s1, s2;
    cudaEvent_t evStart, evZero, evDegE, evGemm, evScan, evFillN;
    SideStream() {
        cudaStreamCreateWithFlags(&s1, cudaStreamNonBlocking);
        cudaStreamCreateWithFlags(&s2, cudaStreamNonBlocking);
        cudaEventCreateWithFlags(&evStart, cudaEventDisableTiming);
        cudaEventCreateWithFlags(&evZero, cudaEventDisableTiming);
        cudaEventCreateWithFlags(&evDegE, cudaEventDisableTiming);
        cudaEventCreateWithFlags(&evGemm, cudaEventDisableTiming);
        cudaEventCreateWithFlags(&evScan, cudaEventDisableTiming);
        cudaEventCreateWithFlags(&evFillN, cudaEventDisableTiming);
    }
};
static SideStream g_ss;

// ---- PTX helpers ----
__device__ __forceinline__ u32 sptr(const void* p) {
    return (u32)__cvta_generic_to_shared(p);
}
__device__ __forceinline__ void ldsm4(u32& r0, u32& r1, u32& r2, u32& r3, u32 a) {
    asm volatile("ldmatrix.sync.aligned.m8n8.x4.shared.b16 {%0,%1,%2,%3},[%4];"
                 : "=r"(r0), "=r"(r1), "=r"(r2), "=r"(r3) : "r"(a));
}
__device__ __forceinline__ void ldsm4t(u32& r0, u32& r1, u32& r2, u32& r3, u32 a) {
    asm volatile("ldmatrix.sync.aligned.m8n8.x4.trans.shared.b16 {%0,%1,%2,%3},[%4];"
                 : "=r"(r0), "=r"(r1), "=r"(r2), "=r"(r3) : "r"(a));
}
__device__ __forceinline__ void mma16816(float* d, const u32* a, const u32* b) {
    asm volatile("mma.sync.aligned.m16n8k16.row.col.f32.f16.f16.f32 "
                 "{%0,%1,%2,%3},{%4,%5,%6,%7},{%8,%9},{%0,%1,%2,%3};"
                 : "+f"(d[0]), "+f"(d[1]), "+f"(d[2]), "+f"(d[3])
                 : "r"(a[0]), "r"(a[1]), "r"(a[2]), "r"(a[3]), "r"(b[0]), "r"(b[1]));
}

// ---- zero counts + dtype detect (block 0) fused ----
__global__ void k_zero_detect(const long long* __restrict__ hei64) {
    int i = blockIdx.x * blockDim.x + threadIdx.x;
    if (i < 2 * NN) g_cnt[i] = 0;
    if (blockIdx.x == 0) {
        int tid = threadIdx.x;
        int bad = 0;
#pragma unroll
        for (int t = 0; t < 16; t++) {
            long long v = hei64[tid * 16 + t];
            if (v < 0 || v >= NN) bad = 1;
        }
        __shared__ int sbad[8];
        unsigned wb = __ballot_sync(0xffffffffu, bad);
        if ((tid & 31) == 0) sbad[tid >> 5] = (wb != 0);
        __syncthreads();
        if (tid == 0) {
            int any = 0;
            for (int w = 0; w < 8; w++) any |= sbad[w];
            g_is_i32 = any;
        }
    }
}

__device__ __forceinline__ int clampi(int v) {
    return (v < 0 || v >= NN) ? 0 : v;
}

// ---- degree counts, split by incidence row, 4 entries/thread ----
__global__ void k_deg_n(const void* __restrict__ hei) {
    int t = blockIdx.x * blockDim.x + threadIdx.x;
    if (t >= NE / 4) return;
    int a, b, c, d;
    if (g_is_i32) {
        int4 v = ((const int4*)hei)[t];
        a = v.x; b = v.y; c = v.z; d = v.w;
    } else {
        longlong2 v0 = ((const longlong2*)hei)[t * 2];
        longlong2 v1 = ((const longlong2*)hei)[t * 2 + 1];
        a = (int)v0.x; b = (int)v0.y; c = (int)v1.x; d = (int)v1.y;
    }
    atomicAdd(&g_cnt[clampi(a)], 1);
    atomicAdd(&g_cnt[clampi(b)], 1);
    atomicAdd(&g_cnt[clampi(c)], 1);
    atomicAdd(&g_cnt[clampi(d)], 1);
}

__global__ void k_deg_e(const void* __restrict__ hei) {
    int t = blockIdx.x * blockDim.x + threadIdx.x;
    if (t >= NE / 4) return;
    int a, b, c, d;
    if (g_is_i32) {
        int4 v = ((const int4*)hei)[NE / 4 + t];
        a = v.x; b = v.y; c = v.z; d = v.w;
    } else {
        longlong2 v0 = ((const longlong2*)hei)[NE / 2 + t * 2];
        longlong2 v1 = ((const longlong2*)hei)[NE / 2 + t * 2 + 1];
        a = (int)v0.x; b = (int)v0.y; c = (int)v1.x; d = (int)v1.y;
    }
    atomicAdd(&g_cnt[NN + clampi(a)], 1);
    atomicAdd(&g_cnt[NN + clampi(b)], 1);
    atomicAdd(&g_cnt[NN + clampi(c)], 1);
    atomicAdd(&g_cnt[NN + clampi(d)], 1);
}

// ---- scan pass A ----
__global__ __launch_bounds__(SCAN_BS) void k_scanA() {
    __shared__ int s[SCAN_BS];
    int blk = blockIdx.x, tid = threadIdx.x;
    int base = blk * SCAN_ELEMS + tid * SCAN_VT;
    int v0 = (base < 2 * NN) ? g_cnt[base] : 0;
    int v1 = (base + 1 < 2 * NN) ? g_cnt[base + 1] : 0;
    int sum = v0 + v1;
    s[tid] = sum;
    __syncthreads();
    for (int off = 1; off < SCAN_BS; off <<= 1) {
        int t = (tid >= off) ? s[tid - off] : 0;
        __syncthreads();
        s[tid] += t;
        __syncthreads();
    }
    if (tid == SCAN_BS - 1) g_bsum[blk] = s[tid];
    int run = s[tid] - sum;
    if (base < 2 * NN) g_offs[base] = run;
    if (base + 1 < 2 * NN) g_offs[base + 1] = run + v0;
}

// ---- scan pass C: fused block-sum scan + offsets finalize + inverse degrees ----
__global__ void k_scanC() {
    __shared__ int sh[256];
    int tid = threadIdx.x;
    sh[tid] = (tid > 0 && tid - 1 < SCAN_NBLK) ? g_bsum[tid - 1] : 0;
    __syncthreads();
    for (int off = 1; off < 256; off <<= 1) {
        int t = (tid >= off) ? sh[tid - off] : 0;
        __syncthreads();
        sh[tid] += t;
        __syncthreads();
    }
    int i = blockIdx.x * blockDim.x + tid;
    if (i < 2 * NN) {
        g_offs[i] += sh[i / SCAN_ELEMS];
        int c = g_cnt[i];
        float inv = c > 0 ? 1.0f / (float)c : 0.0f;
        if (i < NN) g_dinv[i] = inv;
        else        g_binv[i - NN] = inv;
    }
    if (i == 0) g_offs[2 * NN] = 2 * NE;
}

__device__ __forceinline__ void decode(const void* hei, bool i32, int i, int& n, int& e) {
    if (i32) {
        n = ((const int*)hei)[i];
        e = ((const int*)hei)[NE + i];
    } else {
        n = (int)((const long long*)hei)[i];
        e = (int)((const long long*)hei)[NE + i];
    }
    n = clampi(n);
    e = clampi(e);
}

// ---- CSR fill (uint16 payload), split by CSR side ----
__global__ void k_fill_e(const void* __restrict__ hei) {
    int i = blockIdx.x * blockDim.x + threadIdx.x;
    if (i >= NE) return;
    bool i32 = (g_is_i32 != 0);
    int n, e;
    decode(hei, i32, i, n, e);
    int pe = g_offs[NN + e] + atomicSub(&g_cnt[NN + e], 1) - 1;
    g_csr16[pe] = (u16)n;
}

__global__ void k_fill_n(const void* __restrict__ hei) {
    int i = blockIdx.x * blockDim.x + threadIdx.x;
    if (i >= NE) return;
    bool i32 = (g_is_i32 != 0);
    int n, e;
    decode(hei, i32, i, n, e);
    int pn = g_offs[n] + atomicSub(&g_cnt[n], 1) - 1;
    g_csr16[pn] = (u16)e;
}

// ---- fp32 -> fp16 convert ----
__global__ void k_f2h(const float* __restrict__ src, __half* __restrict__ dst, int n4) {
    int i = blockIdx.x * blockDim.x + threadIdx.x;
    if (i < n4) {
        float4 v = ((const float4*)src)[i];
        __half2 h0 = __floats2half2_rn(v.x, v.y);
        __half2 h1 = __floats2half2_rn(v.z, v.w);
        uint2 o;
        o.x = *(u32*)&h0;
        o.y = *(u32*)&h1;
        ((uint2*)dst)[i] = o;
    }
}

// ---- tensor-core GEMM ----
__global__ __launch_bounds__(256) void k_gemm_mma(const __half* __restrict__ A,
                                                  const __half* __restrict__ Wh,
                                                  __half* __restrict__ C, int M) {
    extern __shared__ __half smem[];
    __half* sA = smem;
    __half* sB = smem + 128 * ASTRIDE;
    int tid = threadIdx.x;
    int rb = blockIdx.x * 128;

#pragma unroll
    for (int it = 0; it < 8; it++) {
        int idx = (it * 256 + tid) * 8;
        int r = idx >> 7, c = idx & 127;
        uint4 v = make_uint4(0, 0, 0, 0);
        if (rb + r < M) v = *(const uint4*)(A + (size_t)(rb + r) * HID + c);
        *(uint4*)(sA + r * ASTRIDE + c) = v;
    }
#pragma unroll
    for (int it = 0; it < 8; it++) {
        int idx = (it * 256 + tid) * 8;
        int r = idx >> 7, c = idx & 127;
        *(uint4*)(sB + r * ASTRIDE + c) = *(const uint4*)(Wh + r * HID + c);
    }
    __syncthreads();

    int w = tid >> 5, lane = tid & 31;
    int wm = (w & 3) * 32;
    int wn = (w >> 2) * 64;
    int lrow = (lane & 7) + ((lane >> 3) & 1) * 8;
    int lcol8 = (lane >> 4) * 8;

    float acc[2][8][4];
#pragma unroll
    for (int mi = 0; mi < 2; mi++)
#pragma unroll
        for (int nj = 0; nj < 8; nj++)
#pragma unroll
            for (int q = 0; q < 4; q++) acc[mi][nj][q] = 0.f;

#pragma unroll
    for (int ks = 0; ks < 8; ks++) {
        int k0 = ks * 16;
        u32 a[2][4];
#pragma unroll
        for (int mi = 0; mi < 2; mi++) {
            u32 ad = sptr(sA + (wm + mi * 16 + lrow) * ASTRIDE + k0 + lcol8);
            ldsm4(a[mi][0], a[mi][1], a[mi][2], a[mi][3], ad);
        }
        u32 b[8][2];
#pragma unroll
        for (int nj = 0; nj < 4; nj++) {
            u32 ad = sptr(sB + (k0 + lrow) * ASTRIDE + wn + nj * 16 + lcol8);
            u32 r0, r1, r2, r3;
            ldsm4t(r0, r1, r2, r3, ad);
            b[nj * 2][0] = r0; b[nj * 2][1] = r1;
            b[nj * 2 + 1][0] = r2; b[nj * 2 + 1][1] = r3;
        }
#pragma unroll
        for (int mi = 0; mi < 2; mi++)
#pragma unroll
            for (int nj = 0; nj < 8; nj++)
                mma16816(acc[mi][nj], a[mi], b[nj]);
    }

    int g = lane >> 2, t4 = lane & 3;
#pragma unroll
    for (int mi = 0; mi < 2; mi++) {
        int r0 = rb + wm + mi * 16 + g;
        int r1 = r0 + 8;
#pragma unroll
        for (int nj = 0; nj < 8; nj++) {
            int col = wn + nj * 8 + t4 * 2;
            if (r0 < M) {
                __half2 h = __floats2half2_rn(acc[mi][nj][0], acc[mi][nj][1]);
                *(__half2*)(C + (size_t)r0 * HID + col) = h;
            }
            if (r1 < M) {
                __half2 h = __floats2half2_rn(acc[mi][nj][2], acc[mi][nj][3]);
                *(__half2*)(C + (size_t)r1 * HID + col) = h;
            }
        }
    }
}

// ---- accumulate 8 halfs (uint4) into 8 floats ----
__device__ __forceinline__ void acc_row4(float* acc, uint4 u) {
    const __half2* hp = (const __half2*)&u;
#pragma unroll
    for (int q = 0; q < 4; q++) {
        float2 f = __half22float2(hp[q]);
        acc[2 * q]     += f.x;
        acc[2 * q + 1] += f.y;
    }
}

// ---- edge gather: warp per segment, 16 lanes/row (uint4), 2 rows/iter ----
__global__ __launch_bounds__(256) void k_gather_e(const __half* __restrict__ src,
                                                  __half* __restrict__ dst) {
    int g = blockIdx.x * blockDim.x + threadIdx.x;
    int e = g >> 5;
    int lane = g & 31;
    if (e >= NN) return;
    int beg = g_offs[NN + e];
    int end = g_offs[NN + e + 1];
    int half = lane >> 4, sub = lane & 15;
    float acc[8];
#pragma unroll
    for (int q = 0; q < 8; q++) acc[q] = 0.f;
    const uint4* s4 = (const uint4*)src;  // row = 16 uint4
    int j = beg;
    for (; j + 3 < end; j += 4) {
        int r0 = (int)g_csr16[j + half];
        int r1 = (int)g_csr16[j + 2 + half];
        uint4 u0 = s4[(size_t)r0 * 16 + sub];
        uint4 u1 = s4[(size_t)r1 * 16 + sub];
        acc_row4(acc, u0);
        acc_row4(acc, u1);
    }
    for (; j + 1 < end; j += 2) {
        int r0 = (int)g_csr16[j + half];
        uint4 u0 = s4[(size_t)r0 * 16 + sub];
        acc_row4(acc, u0);
    }
    if (j < end && half == 0) {
        int r0 = (int)g_csr16[j];
        uint4 u0 = s4[(size_t)r0 * 16 + sub];
        acc_row4(acc, u0);
    }
#pragma unroll
    for (int q = 0; q < 8; q++)
        acc[q] += __shfl_xor_sync(0xffffffffu, acc[q], 16);
    if (half == 0) {
        float s = g_binv[e];
        __half2 h[4];
#pragma unroll
        for (int q = 0; q < 4; q++)
            h[q] = __floats2half2_rn(acc[2 * q] * s, acc[2 * q + 1] * s);
        ((uint4*)dst)[(size_t)e * 16 + sub] = *(uint4*)h;
    }
}

// ---- node gather ----
template <bool RES, typename OUT>
__global__ __launch_bounds__(256) void k_gather_n(const __half* __restrict__ src,
                                                  const float* __restrict__ bias,
                                                  const float* __restrict__ pa,
                                                  const float* __restrict__ xres,
                                                  OUT* __restrict__ dst) {
    int g = blockIdx.x * blockDim.x + threadIdx.x;
    int n = g >> 5;
    int lane = g & 31;
    if (n >= NN) return;
    int beg = g_offs[n];
    int end = g_offs[n + 1];
    int half = lane >> 4, sub = lane & 15;
    float acc[8];
#pragma unroll
    for (int q = 0; q < 8; q++) acc[q] = 0.f;
    const uint4* s4 = (const uint4*)src;
    int j = beg;
    for (; j + 3 < end; j += 4) {
        int r0 = (int)g_csr16[j + half];
        int r1 = (int)g_csr16[j + 2 + half];
        uint4 u0 = s4[(size_t)r0 * 16 + sub];
        uint4 u1 = s4[(size_t)r1 * 16 + sub];
        acc_row4(acc, u0);
        acc_row4(acc, u1);
    }
    for (; j + 1 < end; j += 2) {
        int r0 = (int)g_csr16[j + half];
        uint4 u0 = s4[(size_t)r0 * 16 + sub];
        acc_row4(acc, u0);
    }
    if (j < end && half == 0) {
        int r0 = (int)g_csr16[j];
        uint4 u0 = s4[(size_t)r0 * 16 + sub];
        acc_row4(acc, u0);
    }
#pragma unroll
    for (int q = 0; q < 8; q++)
        acc[q] += __shfl_xor_sync(0xffffffffu, acc[q], 16);
    if (half == 0) {
        float d = g_dinv[n];
        float a = pa[0];
        float4 b0 = ((const float4*)bias)[sub * 2];
        float4 b1 = ((const float4*)bias)[sub * 2 + 1];
        float o[8];
        o[0] = acc[0] * d + b0.x; o[1] = acc[1] * d + b0.y;
        o[2] = acc[2] * d + b0.z; o[3] = acc[3] * d + b0.w;
        o[4] = acc[4] * d + b1.x; o[5] = acc[5] * d + b1.y;
        o[6] = acc[6] * d + b1.z; o[7] = acc[7] * d + b1.w;
        if (RES) {
            float4 x0 = ((const float4*)xres)[(size_t)n * 32 + sub * 2];
            float4 x1 = ((const float4*)xres)[(size_t)n * 32 + sub * 2 + 1];
            o[0] += x0.x; o[1] += x0.y; o[2] += x0.z; o[3] += x0.w;
            o[4] += x1.x; o[5] += x1.y; o[6] += x1.z; o[7] += x1.w;
        }
#pragma unroll
        for (int q = 0; q < 8; q++)
            o[q] = o[q] >= 0.f ? o[q] : a * o[q];
        if (sizeof(OUT) == 2) {
            __half2 h[4];
#pragma unroll
            for (int q = 0; q < 4; q++)
                h[q] = __floats2half2_rn(o[2 * q], o[2 * q + 1]);
            ((uint4*)dst)[(size_t)n * 16 + sub] = *(uint4*)h;
        } else {
            float4* dp = (float4*)dst;
            dp[(size_t)n * 32 + sub * 2]     = make_float4(o[0], o[1], o[2], o[3]);
            dp[(size_t)n * 32 + sub * 2 + 1] = make_float4(o[4], o[5], o[6], o[7]);
        }
    }
}

extern "C" void kernel_launch(void* const* d_in, const int* in_sizes, int n_in,
                              void* d_out, int out_size) {
    (void)in_sizes; (void)n_in; (void)out_size;
    const float* x   = (const float*)d_in[0];
    const void*  hei = d_in[1];
    const float* W1  = (const float*)d_in[2];
    const float* b1  = (const float*)d_in[3];
    const float* W2  = (const float*)d_in[4];
    const float* b2  = (const float*)d_in[5];
    const float* pa  = (const float*)d_in[6];
    float* out = (float*)d_out;

    __half *pxh, *pw1h, *pw2h, *pxw, *pm, *ph;
    cudaGetSymbolAddress((void**)&pxh,  g_xh);
    cudaGetSymbolAddress((void**)&pw1h, g_w1h);
    cudaGetSymbolAddress((void**)&pw2h, g_w2h);
    cudaGetSymbolAddress((void**)&pxw,  g_xw);
    cudaGetSymbolAddress((void**)&pm,   g_m);
    cudaGetSymbolAddress((void**)&ph,   g_h);

    const int GW_BLOCKS = (NN * 32) / 256;
    const int GEMM_SMEM = 2 * 128 * ASTRIDE * 2;
    cudaFuncSetAttribute(k_gemm_mma, cudaFuncAttributeMaxDynamicSharedMemorySize, GEMM_SMEM);

    // fork
    cudaEventRecord(g_ss.evStart, 0);
    cudaStreamWaitEvent(g_ss.s1, g_ss.evStart, 0);
    cudaStreamWaitEvent(g_ss.s2, g_ss.evStart, 0);

    // stream 0: zero+detect, node-degree counts
    k_zero_detect<<<(2 * NN + 255) / 256, 256>>>((const long long*)hei);
    cudaEventRecord(g_ss.evZero, 0);
    k_deg_n<<<(NE / 4 + 255) / 256, 256>>>(hei);

    // s2: edge-degree counts (concurrent with deg_n)
    cudaStreamWaitEvent(g_ss.s2, g_ss.evZero, 0);
    k_deg_e<<<(NE / 4 + 255) / 256, 256, 0, g_ss.s2>>>(hei);
    cudaEventRecord(g_ss.evDegE, g_ss.s2);

    // stream 0: scan + edge CSR fill
    cudaStreamWaitEvent(0, g_ss.evDegE, 0);
    k_scanA<<<SCAN_NBLK, SCAN_BS>>>();
    k_scanC<<<(2 * NN + 255) / 256, 256>>>();
    cudaEventRecord(g_ss.evScan, 0);
    k_fill_e<<<(NE + 255) / 256, 256>>>(hei);

    // s1: fp16 conversions + GEMM1, then node CSR fill
    k_f2h<<<(NN * HID / 4 + 255) / 256, 256, 0, g_ss.s1>>>(x, pxh, NN * HID / 4);
    k_f2h<<<(HID * HID / 4 + 255) / 256, 256, 0, g_ss.s1>>>(W1, pw1h, HID * HID / 4);
    k_f2h<<<(HID * HID / 4 + 255) / 256, 256, 0, g_ss.s1>>>(W2, pw2h, HID * HID / 4);
    k_gemm_mma<<<(NN + 127) / 128, 256, GEMM_SMEM, g_ss.s1>>>(pxh, pw1h, pxw, NN);
    cudaEventRecord(g_ss.evGemm, g_ss.s1);
    cudaStreamWaitEvent(g_ss.s1, g_ss.evScan, 0);
    k_fill_n<<<(NE + 255) / 256, 256, 0, g_ss.s1>>>(hei);
    cudaEventRecord(g_ss.evFillN, g_ss.s1);

    // layer 1 aggregation
    cudaStreamWaitEvent(0, g_ss.evGemm, 0);
    k_gather_e<<<GW_BLOCKS, 256>>>(pxw, pm);
    cudaStreamWaitEvent(0, g_ss.evFillN, 0);
    k_gather_n<false, __half><<<GW_BLOCKS, 256>>>(pm, b1, pa, nullptr, ph);

    // layer 2
    k_gemm_mma<<<(NN + 127) / 128, 256, GEMM_SMEM>>>(ph, pw2h, pxw, NN);
    k_gather_e<<<GW_BLOCKS, 256>>>(pxw, pm);
    k_gather_n<true, float><<<GW_BLOCKS, 256>>>(pm, b2, pa, x, out);
}